// round 5
// baseline (speedup 1.0000x reference)
#include <cuda_runtime.h>
#include <math.h>

// Problem constants (fixed by reference)
#define BB   4
#define NN   4096
#define DD   1024
#define HH   16
#define DKC  64
#define MMC  256
#define BN   16384          // B*N
#define BHC  64             // B*H
#define QKVLD 3072          // 3*D

// -------- scratch (device globals; no allocation allowed) --------
__device__ float g_qkv [(size_t)BN * QKVLD];      // 192 MB
__device__ float g_Qf  [(size_t)BHC * NN * MMC];  // 256 MB
__device__ float g_Kf  [(size_t)BHC * NN * MMC];  // 256 MB
__device__ float g_S   [BHC * MMC * DKC];
__device__ float g_Ksum[BHC * MMC];
__device__ float g_ctx [(size_t)BN * DD];
__device__ float g_valid[BN];
__device__ int   g_maskmode;

// -------- mask dtype detection ----------------------------------------------
__global__ void detect_mask_kernel(const unsigned int* __restrict__ m)
{
    __shared__ int sa, sb;
    if (threadIdx.x == 0) { sa = 0; sb = 0; }
    __syncthreads();
    int a = 0, b = 0;
    for (int i = threadIdx.x; i < 4096; i += blockDim.x) {
        unsigned v = m[i];
        if (v == 0x3F800000u) b = 1;
        else if (v > 1u) a = 1;
    }
    if (a) atomicOr(&sa, 1);
    if (b) atomicOr(&sb, 1);
    __syncthreads();
    if (threadIdx.x == 0) g_maskmode = sa ? 1 : (sb ? 2 : 0);
}

__global__ void build_valid_kernel(const void* __restrict__ mask)
{
    int i = blockIdx.x * blockDim.x + threadIdx.x;
    if (i >= BN) return;
    int mode = g_maskmode;
    int pad;
    if (mode == 1)      pad = ((const unsigned char*)mask)[i] != 0;
    else if (mode == 2) pad = ((const float*)mask)[i] != 0.0f;
    else                pad = ((const int*)mask)[i] != 0;
    g_valid[i] = pad ? 0.0f : 1.0f;
}

// ============ split-TF32 tensor-core NT GEMM, static smem (32KB) ============
// C[i][j] = sum_k A[i][k]*B[j][k] + bias[j]
// A: IxK row-major, B: JxK row-major. I,J mult of 128; K mult of 16.
// THREE=1: a=hi+lo split, C = Ahi*Bhi + Ahi*Blo + Alo*Bhi  (fp32 accuracy)
// THREE=0: plain tf32 (used for the output projection; error enters linearly)
// Block tile 128x128x16, 8 warps (2x4), warp tile 64x32.

__device__ __forceinline__ unsigned f2tf(float f)
{
    unsigned u;
    asm("cvt.rna.tf32.f32 %0, %1;" : "=r"(u) : "f"(f));
    return u;
}

// 16-col row swizzle: s=(row>>1)&3; quad = c4^s, elem = (e+s)&3.
// Conflict-free for the float4-sourced scalar stores (distinct quads within a
// row via c4, distinct elems across same-parity rows via s) and for the mma
// fragment loads (distinct quads across same-parity rows, c4 fixed).
__device__ __forceinline__ int sw16(int row, int col)
{
    int c4 = col >> 2, e = col & 3, s = (row >> 1) & 3;
    return row * 16 + (((c4 ^ s) << 2) | ((e + s) & 3));
}

__device__ __forceinline__ void mma_tf32(float* c, const unsigned* a,
                                         const unsigned* b)
{
    asm volatile(
        "mma.sync.aligned.m16n8k8.row.col.f32.tf32.tf32.f32 "
        "{%0,%1,%2,%3}, {%4,%5,%6,%7}, {%8,%9}, {%0,%1,%2,%3};"
        : "+f"(c[0]), "+f"(c[1]), "+f"(c[2]), "+f"(c[3])
        : "r"(a[0]), "r"(a[1]), "r"(a[2]), "r"(a[3]), "r"(b[0]), "r"(b[1]));
}

template<int THREE>
__global__ __launch_bounds__(256)
void gemm_tf32s_kernel(const float* __restrict__ Aparam,
                       const float* __restrict__ Bm,
                       const float* __restrict__ bias,
                       float* __restrict__ Cparam,
                       int I, int J, int K, int useGlobalA, int useGlobalC)
{
    const float* A = useGlobalA ? (const float*)g_ctx : Aparam;
    float*       C = useGlobalC ? (float*)g_qkv : Cparam;

    __shared__ unsigned AsH[128 * 16];
    __shared__ unsigned BsH[128 * 16];
    __shared__ unsigned AsL[THREE ? 128 * 16 : 4];
    __shared__ unsigned BsL[THREE ? 128 * 16 : 4];

    int tid = threadIdx.x;
    int i0 = blockIdx.y * 128, j0 = blockIdx.x * 128;
    int wid = tid >> 5, lane = tid & 31;
    int wm = wid >> 2, wn = wid & 3;          // warp grid 2(m) x 4(n)
    int g = lane >> 2, c = lane & 3;

    float acc[4][4][4];
#pragma unroll
    for (int mt = 0; mt < 4; mt++)
#pragma unroll
        for (int nt = 0; nt < 4; nt++)
#pragma unroll
            for (int e = 0; e < 4; e++) acc[mt][nt][e] = 0.0f;

    for (int k0 = 0; k0 < K; k0 += 16) {
        // ---- load + split-convert A,B tiles (128x16 each) ----
#pragma unroll
        for (int l = 0; l < 2; l++) {
            int idx = tid + l * 256;          // 0..511
            int row = idx >> 2, c4 = idx & 3;
            float4 va = *(const float4*)(A + (size_t)(i0 + row) * K + k0 + c4 * 4);
            float4 vb = *(const float4*)(Bm + (size_t)(j0 + row) * K + k0 + c4 * 4);
            float av[4] = {va.x, va.y, va.z, va.w};
            float bv[4] = {vb.x, vb.y, vb.z, vb.w};
#pragma unroll
            for (int e = 0; e < 4; e++) {
                int p = sw16(row, c4 * 4 + e);
                unsigned ah = f2tf(av[e]);
                unsigned bh = f2tf(bv[e]);
                AsH[p] = ah;
                BsH[p] = bh;
                if (THREE) {
                    AsL[p] = f2tf(av[e] - __uint_as_float(ah));
                    BsL[p] = f2tf(bv[e] - __uint_as_float(bh));
                }
            }
        }
        __syncthreads();

#pragma unroll
        for (int ks = 0; ks < 2; ks++) {
            unsigned afh[4][4], afl[4][4], bfh[4][2], bfl[4][2];
            int col0 = ks * 8 + c;
#pragma unroll
            for (int mt = 0; mt < 4; mt++) {
                int r0 = wm * 64 + mt * 16 + g;
                int p0 = sw16(r0, col0),     p1 = sw16(r0 + 8, col0);
                int p2 = sw16(r0, col0 + 4), p3 = sw16(r0 + 8, col0 + 4);
                afh[mt][0] = AsH[p0]; afh[mt][1] = AsH[p1];
                afh[mt][2] = AsH[p2]; afh[mt][3] = AsH[p3];
                if (THREE) {
                    afl[mt][0] = AsL[p0]; afl[mt][1] = AsL[p1];
                    afl[mt][2] = AsL[p2]; afl[mt][3] = AsL[p3];
                }
            }
#pragma unroll
            for (int nt = 0; nt < 4; nt++) {
                int rb = wn * 32 + nt * 8 + g;
                int p0 = sw16(rb, col0), p1 = sw16(rb, col0 + 4);
                bfh[nt][0] = BsH[p0]; bfh[nt][1] = BsH[p1];
                if (THREE) {
                    bfl[nt][0] = BsL[p0]; bfl[nt][1] = BsL[p1];
                }
            }
#pragma unroll
            for (int mt = 0; mt < 4; mt++)
#pragma unroll
                for (int nt = 0; nt < 4; nt++) {
                    if (THREE) {
                        mma_tf32(acc[mt][nt], afh[mt], bfl[nt]);  // hi*lo
                        mma_tf32(acc[mt][nt], afl[mt], bfh[nt]);  // lo*hi
                    }
                    mma_tf32(acc[mt][nt], afh[mt], bfh[nt]);      // hi*hi
                }
        }
        __syncthreads();
    }

    // ---- epilogue: add bias, store ----
#pragma unroll
    for (int nt = 0; nt < 4; nt++) {
        int col = j0 + wn * 32 + nt * 8 + 2 * c;
        float b0 = bias[col], b1 = bias[col + 1];
#pragma unroll
        for (int mt = 0; mt < 4; mt++) {
            int row = i0 + wm * 64 + mt * 16 + g;
            float2 v0 = make_float2(acc[mt][nt][0] + b0, acc[mt][nt][1] + b1);
            float2 v1 = make_float2(acc[mt][nt][2] + b0, acc[mt][nt][3] + b1);
            *(float2*)(C + (size_t)row * J + col)       = v0;
            *(float2*)(C + (size_t)(row + 8) * J + col) = v1;
        }
    }
}

// -------- phi kernel (fp32, unchanged) --------------------------------------
__global__ __launch_bounds__(256)
void phi_kernel(const float* __restrict__ omega, int qoff, int isQ)
{
    __shared__ float omT[MMC * 33];
    __shared__ float tS[32 * 64];
    __shared__ float sqS[32];
    __shared__ float vS[32];

    int tid = threadIdx.x;
    int w = tid >> 5, lane = tid & 31;
    int bh = blockIdx.y;
    int b = bh / HH, h = bh % HH;
    int n0 = blockIdx.x * 32;

    float* F = isQ ? (float*)g_Qf : (float*)g_Kf;
    const float* Tbase = (const float*)g_qkv + qoff;

    {
        int r = tid >> 3;
        int ks = (tid & 7) * 8;
        size_t rowoff = ((size_t)(b * NN + n0 + r)) * QKVLD + h * DKC;
        float vl = g_valid[b * NN + n0 + r];
        float4 a = *(const float4*)(Tbase + rowoff + ks);
        float4 c = *(const float4*)(Tbase + rowoff + ks + 4);
        if (isQ) {
            a.x *= vl; a.y *= vl; a.z *= vl; a.w *= vl;
            c.x *= vl; c.y *= vl; c.z *= vl; c.w *= vl;
        }
        *(float4*)&tS[r * 64 + ks]     = a;
        *(float4*)&tS[r * 64 + ks + 4] = c;
        float p = a.x*a.x + a.y*a.y + a.z*a.z + a.w*a.w
                + c.x*c.x + c.y*c.y + c.z*c.z + c.w*c.w;
        p += __shfl_xor_sync(0xffffffffu, p, 1);
        p += __shfl_xor_sync(0xffffffffu, p, 2);
        p += __shfl_xor_sync(0xffffffffu, p, 4);
        if ((tid & 7) == 0) { sqS[r] = 0.5f * p; vS[r] = vl; }
    }

    float acc[4][8];
#pragma unroll
    for (int i = 0; i < 4; i++)
#pragma unroll
        for (int j = 0; j < 8; j++) acc[i][j] = 0.0f;

    for (int kc = 0; kc < DKC; kc += 32) {
        if (kc) __syncthreads();
#pragma unroll
        for (int i = 0; i < 32; i++) {
            int m = w * 32 + i;
            omT[m * 33 + lane] = omega[((size_t)(h * MMC + m)) * DKC + kc + lane];
        }
        __syncthreads();
#pragma unroll
        for (int kk = 0; kk < 32; kk++) {
            float tv[4];
#pragma unroll
            for (int i = 0; i < 4; i++) tv[i] = tS[(w * 4 + i) * 64 + kc + kk];
#pragma unroll
            for (int j = 0; j < 8; j++) {
                float ov = omT[(lane + j * 32) * 33 + kk];
#pragma unroll
                for (int i = 0; i < 4; i++)
                    acc[i][j] = fmaf(tv[i], ov, acc[i][j]);
            }
        }
    }

#pragma unroll
    for (int i = 0; i < 4; i++) {
        float rm = acc[i][0];
#pragma unroll
        for (int j = 1; j < 8; j++) rm = fmaxf(rm, acc[i][j]);
        rm = fmaxf(rm, __shfl_xor_sync(0xffffffffu, rm, 16));
        rm = fmaxf(rm, __shfl_xor_sync(0xffffffffu, rm, 8));
        rm = fmaxf(rm, __shfl_xor_sync(0xffffffffu, rm, 4));
        rm = fmaxf(rm, __shfl_xor_sync(0xffffffffu, rm, 2));
        rm = fmaxf(rm, __shfl_xor_sync(0xffffffffu, rm, 1));
        int r = w * 4 + i;
        float sq = sqS[r];
        float vp = isQ ? 1.0f : vS[r];
        size_t base = ((size_t)bh * NN + n0 + r) * MMC;
#pragma unroll
        for (int j = 0; j < 8; j++)
            F[base + lane + j * 32] = expf(acc[i][j] - rm - sq) * 0.0625f * vp;
    }
}

// -------- S kernel (unchanged) ----------------------------------------------
__global__ __launch_bounds__(256)
void s_kernel()
{
    __shared__ float Ks[32][68];
    __shared__ float Vs[32][68];
    int tid = threadIdx.x;
    int bh = blockIdx.y;
    int m0 = blockIdx.x * 64;
    int b = bh / HH, h = bh % HH;
    int dt = tid & 15, mt = tid >> 4;

    const float* Vbase = (const float*)g_qkv + 2 * DD;

    float acc[4][4];
#pragma unroll
    for (int i = 0; i < 4; i++)
#pragma unroll
        for (int j = 0; j < 4; j++) acc[i][j] = 0.0f;
    float ks[4] = {0.f, 0.f, 0.f, 0.f};

    size_t kfbase = ((size_t)bh * NN) * MMC + m0;

    for (int n0 = 0; n0 < NN; n0 += 32) {
        int r = tid >> 3, c = (tid & 7) * 8;
        {
            float4 a = *(const float4*)&g_Kf[kfbase + (size_t)(n0 + r) * MMC + c];
            float4 d = *(const float4*)&g_Kf[kfbase + (size_t)(n0 + r) * MMC + c + 4];
            *(float4*)&Ks[r][c]     = a;
            *(float4*)&Ks[r][c + 4] = d;
            size_t voff = ((size_t)(b * NN + n0 + r)) * QKVLD + h * DKC;
            float4 va = *(const float4*)(Vbase + voff + c);
            float4 vd = *(const float4*)(Vbase + voff + c + 4);
            *(float4*)&Vs[r][c]     = va;
            *(float4*)&Vs[r][c + 4] = vd;
        }
        __syncthreads();
#pragma unroll
        for (int nn = 0; nn < 32; nn++) {
            float4 kf = *(const float4*)&Ks[nn][mt * 4];
            float4 vv = *(const float4*)&Vs[nn][dt * 4];
            float kfa[4] = {kf.x, kf.y, kf.z, kf.w};
            float vva[4] = {vv.x, vv.y, vv.z, vv.w};
#pragma unroll
            for (int i = 0; i < 4; i++) {
                ks[i] += kfa[i];
#pragma unroll
                for (int j = 0; j < 4; j++)
                    acc[i][j] = fmaf(kfa[i], vva[j], acc[i][j]);
            }
        }
        __syncthreads();
    }
#pragma unroll
    for (int i = 0; i < 4; i++) {
        int m = m0 + mt * 4 + i;
        *(float4*)&g_S[((size_t)bh * MMC + m) * DKC + dt * 4] =
            make_float4(acc[i][0], acc[i][1], acc[i][2], acc[i][3]);
        if (dt == 0) g_Ksum[bh * MMC + m] = ks[i];
    }
}

// -------- ctx kernel (unchanged) --------------------------------------------
__global__ __launch_bounds__(256)
void ctx_kernel()
{
    __shared__ float Ssh[64][68];
    __shared__ float Qs[64][68];
    __shared__ float KsumS[64];
    __shared__ float denomS[64];
    __shared__ float vSh[64];

    int tid = threadIdx.x;
    int bh = blockIdx.y;
    int n0 = blockIdx.x * 64;
    int b = bh / HH, h = bh % HH;
    int dt = tid & 15, rt = tid >> 4;

    if (tid < 64) vSh[tid] = g_valid[b * NN + n0 + tid];

    float acc[4][4];
#pragma unroll
    for (int i = 0; i < 4; i++)
#pragma unroll
        for (int j = 0; j < 4; j++) acc[i][j] = 0.0f;
    float dacc[4] = {0.f, 0.f, 0.f, 0.f};

    for (int mc = 0; mc < MMC; mc += 64) {
        __syncthreads();
#pragma unroll
        for (int l = 0; l < 4; l++) {
            int f = tid + l * 256;
            int mr = f >> 4, c = (f & 15) * 4;
            float4 sv = *(const float4*)&g_S[((size_t)bh * MMC + mc + mr) * DKC + c];
            *(float4*)&Ssh[mr][c] = sv;
            float4 qv = *(const float4*)&g_Qf[((size_t)bh * NN + n0 + mr) * MMC + mc + c];
            *(float4*)&Qs[mr][c] = qv;
        }
        if (tid < 64) KsumS[tid] = g_Ksum[bh * MMC + mc + tid];
        __syncthreads();
#pragma unroll 8
        for (int mm = 0; mm < 64; mm++) {
            float q[4];
#pragma unroll
            for (int i = 0; i < 4; i++) q[i] = Qs[rt * 4 + i][mm];
            float4 s4 = *(const float4*)&Ssh[mm][dt * 4];
            float km = KsumS[mm];
#pragma unroll
            for (int i = 0; i < 4; i++) {
                dacc[i] = fmaf(q[i], km, dacc[i]);
                acc[i][0] = fmaf(q[i], s4.x, acc[i][0]);
                acc[i][1] = fmaf(q[i], s4.y, acc[i][1]);
                acc[i][2] = fmaf(q[i], s4.z, acc[i][2]);
                acc[i][3] = fmaf(q[i], s4.w, acc[i][3]);
            }
        }
    }
    if (dt == 0) {
#pragma unroll
        for (int i = 0; i < 4; i++) denomS[rt * 4 + i] = dacc[i] + 1e-6f;
    }
    __syncthreads();
#pragma unroll
    for (int i = 0; i < 4; i++) {
        int r = rt * 4 + i;
        float inv = 1.0f / denomS[r];
        float vl = vSh[r];
        size_t off = ((size_t)(b * NN + n0 + r)) * DD + h * DKC + dt * 4;
        *(float4*)&g_ctx[off] = make_float4(acc[i][0] * inv * vl,
                                            acc[i][1] * inv * vl,
                                            acc[i][2] * inv * vl,
                                            acc[i][3] * inv * vl);
    }
}

// ---------------------------------------------------------------------------
// kernel_launch: KERNEL LAUNCHES ONLY. Any other CUDA runtime API call here
// crashes the harness container (observed R1: cudaGetSymbolAddress, R4:
// cudaFuncSetAttribute). Do not add host API calls.
extern "C" void kernel_launch(void* const* d_in, const int* in_sizes, int n_in,
                              void* d_out, int out_size)
{
    const float* x     = (const float*)d_in[0];
    const float* Wqkv  = (const float*)d_in[1];
    const float* bqkv  = (const float*)d_in[2];
    const float* Wout  = (const float*)d_in[3];
    const float* bout  = (const float*)d_in[4];
    const float* omega = (const float*)d_in[5];
    const void*  mask  = d_in[6];
    float* out = (float*)d_out;

    detect_mask_kernel<<<1, 256>>>((const unsigned int*)mask);
    build_valid_kernel<<<BN / 256, 256>>>(mask);

    // QKV projection: g_qkv = x @ Wqkv^T + bqkv  (3-term split-tf32 = fp32 acc)
    gemm_tf32s_kernel<1><<<dim3(QKVLD / 128, BN / 128), 256>>>(
        x, Wqkv, bqkv, nullptr, BN, QKVLD, DD, 0, 1);

    // phi(Q) (pre-masked) -> g_Qf, phi(K) (post-masked) -> g_Kf
    dim3 gp(NN / 32, BHC);
    phi_kernel<<<gp, 256>>>(omega, 0,  1);
    phi_kernel<<<gp, 256>>>(omega, DD, 0);

    // S and Ksum
    s_kernel<<<dim3(MMC / 64, BHC), 256>>>();

    // ctx
    ctx_kernel<<<dim3(NN / 64, BHC), 256>>>();

    // out = g_ctx @ Wout^T + bout  (1-term tf32; linear error path, ~1.7e-4)
    gemm_tf32s_kernel<0><<<dim3(DD / 128, BN / 128), 256>>>(
        nullptr, Wout, bout, out, BN, DD, DD, 1, 0);
}